// round 11
// baseline (speedup 1.0000x reference)
#include <cuda_runtime.h>
#include <cuda_bf16.h>
#include <cstdint>

#define HID   1024
#define NST   16
#define BATCHN 4
#define SEQ   2048
#define XPC   (2*NST + HID)          // 1056
#define NPAD1 1152                   // Wx rows padded to 9*128
#define M_ROWS (BATCHN*SEQ)          // 8192
#define NCHUNK 64
#define LC    (SEQ/NCHUNK)           // 32

// ---------------- scratch (no allocations allowed) ----------------
__device__ float g_xp[M_ROWS * XPC];                 // x @ Wx^T (fp32)
__device__ float g_dt[M_ROWS * HID];                 // cached softplus(delta)
__device__ float g_E [NCHUNK*BATCHN*NST*HID];
__device__ float g_S [NCHUNK*BATCHN*HID];
__device__ float g_h0[NCHUNK*BATCHN*NST*HID];
// pre-split bf16 operands
__device__ __nv_bfloat16 g_xh[M_ROWS*HID],  g_xl[M_ROWS*HID];
__device__ __nv_bfloat16 g_wxh[NPAD1*HID],  g_wxl[NPAD1*HID];
__device__ __nv_bfloat16 g_wh[HID*HID],     g_wl[HID*HID];
__device__ __nv_bfloat16 g_yh[M_ROWS*HID],  g_yl[M_ROWS*HID];

// ---------------- helpers ----------------
__device__ __forceinline__ float ex2_(float x) {
    float y;
    asm("ex2.approx.ftz.f32 %0, %1;" : "=f"(y) : "f"(x));
    return y;
}
__device__ __forceinline__ uint32_t smem_u32(const void* p) {
    uint32_t a;
    asm("{ .reg .u64 t; cvta.to.shared.u64 t, %1; cvt.u32.u64 %0, t; }"
        : "=r"(a) : "l"(p));
    return a;
}
#define SMEM_SWZ(off) ((off) ^ (((off) >> 3) & 0x70))

__device__ __forceinline__ void ldsm4(uint32_t addr, uint32_t* r) {
    asm volatile("ldmatrix.sync.aligned.m8n8.x4.shared.b16 {%0,%1,%2,%3}, [%4];"
                 : "=r"(r[0]), "=r"(r[1]), "=r"(r[2]), "=r"(r[3]) : "r"(addr));
}
__device__ __forceinline__ void mma_bf16(float* c, const uint32_t* a,
                                         uint32_t b0, uint32_t b1) {
    asm volatile(
        "mma.sync.aligned.m16n8k16.row.col.f32.bf16.bf16.f32 "
        "{%0,%1,%2,%3}, {%4,%5,%6,%7}, {%8,%9}, {%0,%1,%2,%3};"
        : "+f"(c[0]), "+f"(c[1]), "+f"(c[2]), "+f"(c[3])
        : "r"(a[0]), "r"(a[1]), "r"(a[2]), "r"(a[3]), "r"(b0), "r"(b1));
}
__device__ __forceinline__ void cp16(uint32_t dst, const void* src) {
    asm volatile("cp.async.cg.shared.global [%0], [%1], 16;"
                 :: "r"(dst), "l"(src) : "memory");
}
#define CP_COMMIT() asm volatile("cp.async.commit_group;" ::: "memory")
#define CP_WAIT(n)  asm volatile("cp.async.wait_group %0;" :: "n"(n) : "memory")

// ================== split: fp32 -> (hi, lo) bf16 ==================
__global__ __launch_bounds__(256)
void split_f32(const float* __restrict__ src, __nv_bfloat16* __restrict__ hi,
               __nv_bfloat16* __restrict__ lo, int nsrc, int ntot) {
    int i = (blockIdx.x * 256 + threadIdx.x) * 4;
    if (i >= ntot) return;
    float4 v = (i < nsrc) ? *(const float4*)&src[i]
                          : make_float4(0.f, 0.f, 0.f, 0.f);
    float vs[4] = {v.x, v.y, v.z, v.w};
    union { __nv_bfloat16 b[4]; uint2 u; } ph, pl;
#pragma unroll
    for (int j = 0; j < 4; j++) {
        __nv_bfloat16 h = __float2bfloat16(vs[j]);
        ph.b[j] = h;
        pl.b[j] = __float2bfloat16(vs[j] - __bfloat162float(h));
    }
    *(uint2*)&hi[i] = ph.u;
    *(uint2*)&lo[i] = pl.u;
}

// ========== GEMM: C[M,N] = A[M,K]*B[N,K]^T, pre-split bf16, cp.async ==========
// 256 threads, BM=128, BN=64, BK=32, 4 stages -> 2 CTAs/SM.
// SMEM row (128B): [hi 64B | lo 64B], SW128 swizzle.
#define GBK2   32
#define ATILE  16384                  // 128 rows * 128B
#define BTILE  8192                   // 64 rows * 128B
#define STAGEB (ATILE + BTILE)        // 24KB
#define STAGES 4
#define GEMM_DSMEM (STAGES*STAGEB + 1024)

__global__ __launch_bounds__(256, 2)
void gemm_nt(const __nv_bfloat16* __restrict__ Ah, const __nv_bfloat16* __restrict__ Al,
             const __nv_bfloat16* __restrict__ Bh, const __nv_bfloat16* __restrict__ Bl,
             float* __restrict__ C, int M, int N, int K, int ldc) {
    extern __shared__ char dsm_raw[];
    const uint32_t dsm = (smem_u32(dsm_raw) + 1023u) & ~1023u;

    const int tid  = threadIdx.x;
    const int lane = tid & 31;
    const int warp = tid >> 5;           // 0..7
    const int wm   = warp >> 1;          // 0..3 -> 32-row band
    const int wn   = warp & 1;           // 0..1 -> 32-col band
    const int bm   = blockIdx.y * 128;
    const int bn   = blockIdx.x * 64;
    const int nk   = K / GBK2;

    // cp.async mapping:
    // A: 128 rows x 8 chunks(16B) = 1024 -> 4/thread (contiguous 64B)
    const int ar   = tid >> 1;           // 0..127
    const int ac0  = (tid & 1) * 4;      // 0 or 4
    // B: 64 rows x 8 chunks = 512 -> 2/thread
    const int br   = tid >> 2;           // 0..63
    const int bc0  = (tid & 3) * 2;      // 0,2,4,6

    float acc[2][4][4];
#pragma unroll
    for (int a = 0; a < 2; a++)
#pragma unroll
        for (int b = 0; b < 4; b++)
#pragma unroll
            for (int c = 0; c < 4; c++) acc[a][b][c] = 0.f;

    auto issue = [&](int kt) {
        const uint32_t sA = dsm + (uint32_t)(kt % STAGES) * STAGEB;
        const uint32_t sB = sA + ATILE;
        const int kb = kt * GBK2;
        {
            const __nv_bfloat16* base = (ac0 < 4 ? Ah : Al)
                + (size_t)(bm + ar) * K + kb;
#pragma unroll
            for (int q = 0; q < 4; q++) {
                const int c = ac0 + q;                 // 0..7
                cp16(sA + SMEM_SWZ((uint32_t)(ar * 128 + c * 16)),
                     base + (c & 3) * 8);
            }
        }
        {
            const __nv_bfloat16* base = (bc0 < 4 ? Bh : Bl)
                + (size_t)(bn + br) * K + kb;
#pragma unroll
            for (int q = 0; q < 2; q++) {
                const int c = bc0 + q;
                cp16(sB + SMEM_SWZ((uint32_t)(br * 128 + c * 16)),
                     base + (c & 3) * 8);
            }
        }
    };

    issue(0); CP_COMMIT();
    issue(1); CP_COMMIT();
    issue(2); CP_COMMIT();

    for (int kt = 0; kt < nk; kt++) {
        CP_WAIT(2);
        __syncthreads();
        if (kt + 3 < nk) issue(kt + 3);
        CP_COMMIT();

        const uint32_t sA = dsm + (uint32_t)(kt % STAGES) * STAGEB;
        const uint32_t sB = sA + ATILE;
#pragma unroll
        for (int kk = 0; kk < 64; kk += 32) {        // byte offset of k16 slice
            uint32_t ah[2][4], alr[2][4], bh[2][4], bl[2][4];
#pragma unroll
            for (int mi = 0; mi < 2; mi++) {
                const uint32_t row = wm * 32 + mi * 16 + (lane & 15);
                const uint32_t o = row * 128 + kk + ((lane >> 4) << 4);
                ldsm4(sA + SMEM_SWZ(o),      ah[mi]);
                ldsm4(sA + SMEM_SWZ(o + 64), alr[mi]);
            }
#pragma unroll
            for (int ng = 0; ng < 2; ng++) {
                const uint32_t row = wn * 32 + ng * 16 + (lane & 7)
                                   + (((lane >> 4) & 1) << 3);
                const uint32_t o = row * 128 + kk + (((lane >> 3) & 1) << 4);
                ldsm4(sB + SMEM_SWZ(o),      bh[ng]);
                ldsm4(sB + SMEM_SWZ(o + 64), bl[ng]);
            }
#pragma unroll
            for (int mi = 0; mi < 2; mi++)
#pragma unroll
                for (int nj = 0; nj < 4; nj++) {
                    const int ng = nj >> 1, hf = nj & 1;
                    mma_bf16(acc[mi][nj], ah[mi],  bh[ng][hf*2], bh[ng][hf*2+1]);
                    mma_bf16(acc[mi][nj], ah[mi],  bl[ng][hf*2], bl[ng][hf*2+1]);
                    mma_bf16(acc[mi][nj], alr[mi], bh[ng][hf*2], bh[ng][hf*2+1]);
                }
        }
        __syncthreads();
    }

    // epilogue
#pragma unroll
    for (int mi = 0; mi < 2; mi++)
#pragma unroll
        for (int nj = 0; nj < 4; nj++) {
            const int row = bm + wm * 32 + mi * 16 + (lane >> 2);
            const int col = bn + wn * 32 + nj * 8 + ((lane & 3) << 1);
            if (col < N) {
                *(float2*)&C[(size_t)row * ldc + col] =
                    make_float2(acc[mi][nj][0], acc[mi][nj][1]);
                *(float2*)&C[(size_t)(row + 8) * ldc + col] =
                    make_float2(acc[mi][nj][2], acc[mi][nj][3]);
            }
        }
}

// ---------------- scan ----------------
__device__ __forceinline__ float softplus_(float v) {
    return fmaxf(v, 0.f) + __logf(1.f + __expf(-fabsf(v)));
}

__global__ __launch_bounds__(256)
void scan_pass1(const float* __restrict__ x, const float* __restrict__ A_log) {
    const int h = blockIdx.x * 256 + threadIdx.x;
    const int b = blockIdx.y, c = blockIdx.z;
    const int m0 = b * SEQ + c * LC;

    __shared__ float bt_s[LC][NST];
    for (int i = threadIdx.x; i < LC * NST; i += 256) {
        int t = i >> 4, j = i & 15;
        bt_s[t][j] = g_xp[(size_t)(m0 + t) * XPC + j];
    }
    float A2[NST];
#pragma unroll
    for (int n = 0; n < NST; n++) A2[n] = -__expf(A_log[n]) * 1.44269504f;
    __syncthreads();

    float E[NST];
#pragma unroll
    for (int n = 0; n < NST; n++) E[n] = 0.f;
    float S = 0.f;

#pragma unroll 2
    for (int t = 0; t < LC; t++) {
        float dtr = g_xp[(size_t)(m0 + t) * XPC + 2*NST + h];
        float dt  = softplus_(dtr);
        float xv  = x[(size_t)(m0 + t) * HID + h];
        g_dt[(size_t)(m0 + t) * HID + h] = dt;
        S += dt;
        float dtx = dt * xv;
#pragma unroll
        for (int n = 0; n < NST; n++) {
            float dA = ex2_(A2[n] * dt);
            E[n] = fmaf(dA, E[n], bt_s[t][n] * dtx);
        }
    }
    const int cb = c * BATCHN + b;
#pragma unroll
    for (int n = 0; n < NST; n++)
        g_E[((size_t)cb * NST + n) * HID + h] = E[n];
    g_S[(size_t)cb * HID + h] = S;
}

__global__ __launch_bounds__(256)
void scan_combine(const float* __restrict__ A_log) {
    const int idx = blockIdx.x * 256 + threadIdx.x;
    const int h = idx & (HID - 1);
    const int n = (idx >> 10) & (NST - 1);
    const int b = idx >> 14;
    const float A2 = -__expf(A_log[n]) * 1.44269504f;

    float hr = 0.f;
    float Ecur = g_E[((size_t)(0 * BATCHN + b) * NST + n) * HID + h];
    float Scur = g_S[(size_t)(0 * BATCHN + b) * HID + h];

    for (int c = 0; c < NCHUNK; c++) {
        float Enext = 0.f, Snext = 0.f;
        if (c + 1 < NCHUNK) {
            const int cb1 = (c + 1) * BATCHN + b;
            Enext = g_E[((size_t)cb1 * NST + n) * HID + h];
            Snext = g_S[(size_t)cb1 * HID + h];
        }
        const int cb = c * BATCHN + b;
        g_h0[((size_t)cb * NST + n) * HID + h] = hr;
        hr = fmaf(ex2_(A2 * Scur), hr, Ecur);
        Ecur = Enext; Scur = Snext;
    }
}

// pass 2 -> writes split bf16 y directly (GEMM2's A operand)
__global__ __launch_bounds__(256)
void scan_pass2(const float* __restrict__ x, const float* __restrict__ A_log,
                const float* __restrict__ Dw) {
    const int h = blockIdx.x * 256 + threadIdx.x;
    const int b = blockIdx.y, c = blockIdx.z;
    const int m0 = b * SEQ + c * LC;

    __shared__ float bc_s[LC][2 * NST];
    for (int i = threadIdx.x; i < LC * 2 * NST; i += 256) {
        int t = i >> 5, j = i & 31;
        bc_s[t][j] = g_xp[(size_t)(m0 + t) * XPC + j];
    }
    float A2[NST];
#pragma unroll
    for (int n = 0; n < NST; n++) A2[n] = -__expf(A_log[n]) * 1.44269504f;
    __syncthreads();

    const int cb = c * BATCHN + b;
    float hreg[NST];
#pragma unroll
    for (int n = 0; n < NST; n++)
        hreg[n] = g_h0[((size_t)cb * NST + n) * HID + h];
    const float Dh = Dw[h];

#pragma unroll 2
    for (int t = 0; t < LC; t++) {
        float dt  = g_dt[(size_t)(m0 + t) * HID + h];
        float xv  = x[(size_t)(m0 + t) * HID + h];
        float dtx = dt * xv;
        float y   = Dh * xv;
#pragma unroll
        for (int n = 0; n < NST; n++) {
            float dA = ex2_(A2[n] * dt);
            hreg[n] = fmaf(dA, hreg[n], bc_s[t][n] * dtx);
            y = fmaf(bc_s[t][NST + n], hreg[n], y);
        }
        __nv_bfloat16 hb = __float2bfloat16(y);
        const size_t o = (size_t)(m0 + t) * HID + h;
        g_yh[o] = hb;
        g_yl[o] = __float2bfloat16(y - __bfloat162float(hb));
    }
}

// ---------------- launch ----------------
extern "C" void kernel_launch(void* const* d_in, const int* in_sizes, int n_in,
                              void* d_out, int out_size) {
    const float* x    = (const float*)d_in[0];
    const float* Wx   = (const float*)d_in[1];
    const float* Alog = (const float*)d_in[2];
    const float* Dw   = (const float*)d_in[3];
    const float* Wout = (const float*)d_in[4];
    for (int i = 0; i < n_in; i++) {
        const float* p = (const float*)d_in[i];
        switch (in_sizes[i]) {
            case M_ROWS * HID: x    = p; break;
            case XPC * HID:    Wx   = p; break;
            case NST:          Alog = p; break;
            case HID:          Dw   = p; break;
            case HID * HID:    Wout = p; break;
        }
    }

    float* xp_d = nullptr;
    cudaGetSymbolAddress((void**)&xp_d, g_xp);
    __nv_bfloat16 *xh, *xl, *wxh, *wxl, *wh, *wl, *yh, *yl;
    cudaGetSymbolAddress((void**)&xh,  g_xh);
    cudaGetSymbolAddress((void**)&xl,  g_xl);
    cudaGetSymbolAddress((void**)&wxh, g_wxh);
    cudaGetSymbolAddress((void**)&wxl, g_wxl);
    cudaGetSymbolAddress((void**)&wh,  g_wh);
    cudaGetSymbolAddress((void**)&wl,  g_wl);
    cudaGetSymbolAddress((void**)&yh,  g_yh);
    cudaGetSymbolAddress((void**)&yl,  g_yl);

    cudaFuncSetAttribute(gemm_nt, cudaFuncAttributeMaxDynamicSharedMemorySize,
                         GEMM_DSMEM);

    dim3 blk(256);
    // pre-split operands
    split_f32<<<M_ROWS*HID/1024, blk>>>(x,    xh,  xl,  M_ROWS*HID, M_ROWS*HID);
    split_f32<<<NPAD1*HID/1024,  blk>>>(Wx,   wxh, wxl, XPC*HID,    NPAD1*HID);
    split_f32<<<HID*HID/1024,    blk>>>(Wout, wh,  wl,  HID*HID,    HID*HID);

    // GEMM1: g_xp = x @ Wx^T   (M=8192, N=1056 padded 1152, K=1024)
    gemm_nt<<<dim3(NPAD1/64, M_ROWS/128), blk, GEMM_DSMEM>>>(
        xh, xl, wxh, wxl, xp_d, M_ROWS, XPC, HID, XPC);

    // chunked selective scan
    scan_pass1 <<<dim3(HID / 256, BATCHN, NCHUNK), blk>>>(x, Alog);
    scan_combine<<<BATCHN * NST * HID / 256, blk>>>(Alog);
    scan_pass2 <<<dim3(HID / 256, BATCHN, NCHUNK), blk>>>(x, Alog, Dw);

    // GEMM2: out = y @ Wout^T  (M=8192, N=1024, K=1024)
    gemm_nt<<<dim3(HID/64, M_ROWS/128), blk, GEMM_DSMEM>>>(
        yh, yl, wh, wl, (float*)d_out, M_ROWS, HID, HID, HID);
}

// round 13
// speedup vs baseline: 1.1374x; 1.1374x over previous
#include <cuda_runtime.h>
#include <cuda_bf16.h>
#include <cstdint>

#define HID   1024
#define NST   16
#define BATCHN 4
#define SEQ   2048
#define XPC   (2*NST + HID)          // 1056
#define NPAD1 1152                   // Wx rows padded to 9*128
#define M_ROWS (BATCHN*SEQ)          // 8192
#define NCHUNK 64
#define LC    (SEQ/NCHUNK)           // 32

// ---------------- scratch (no allocations allowed) ----------------
__device__ float g_xp[M_ROWS * XPC];                 // x @ Wx^T (fp32)
__device__ float g_dt[M_ROWS * HID];                 // cached softplus(delta)
__device__ float g_E [NCHUNK*BATCHN*NST*HID];
__device__ float g_S [NCHUNK*BATCHN*HID];
__device__ float g_h0[NCHUNK*BATCHN*NST*HID];
// pre-split bf16 operands
__device__ __nv_bfloat16 g_xh[M_ROWS*HID],  g_xl[M_ROWS*HID];
__device__ __nv_bfloat16 g_wxh[NPAD1*HID],  g_wxl[NPAD1*HID];
__device__ __nv_bfloat16 g_wh[HID*HID],     g_wl[HID*HID];
__device__ __nv_bfloat16 g_yh[M_ROWS*HID],  g_yl[M_ROWS*HID];

// ---------------- helpers ----------------
__device__ __forceinline__ float ex2_(float x) {
    float y;
    asm("ex2.approx.ftz.f32 %0, %1;" : "=f"(y) : "f"(x));
    return y;
}
__device__ __forceinline__ uint32_t smem_u32(const void* p) {
    uint32_t a;
    asm("{ .reg .u64 t; cvta.to.shared.u64 t, %1; cvt.u32.u64 %0, t; }"
        : "=r"(a) : "l"(p));
    return a;
}
#define SMEM_SWZ(off) ((off) ^ (((off) >> 3) & 0x70))

__device__ __forceinline__ void ldsm4(uint32_t addr, uint32_t* r) {
    asm volatile("ldmatrix.sync.aligned.m8n8.x4.shared.b16 {%0,%1,%2,%3}, [%4];"
                 : "=r"(r[0]), "=r"(r[1]), "=r"(r[2]), "=r"(r[3]) : "r"(addr));
}
__device__ __forceinline__ void mma_bf16(float* c, const uint32_t* a,
                                         uint32_t b0, uint32_t b1) {
    asm volatile(
        "mma.sync.aligned.m16n8k16.row.col.f32.bf16.bf16.f32 "
        "{%0,%1,%2,%3}, {%4,%5,%6,%7}, {%8,%9}, {%0,%1,%2,%3};"
        : "+f"(c[0]), "+f"(c[1]), "+f"(c[2]), "+f"(c[3])
        : "r"(a[0]), "r"(a[1]), "r"(a[2]), "r"(a[3]), "r"(b0), "r"(b1));
}
__device__ __forceinline__ void cp16(uint32_t dst, const void* src) {
    asm volatile("cp.async.cg.shared.global [%0], [%1], 16;"
                 :: "r"(dst), "l"(src) : "memory");
}
#define CP_COMMIT() asm volatile("cp.async.commit_group;" ::: "memory")
#define CP_WAIT(n)  asm volatile("cp.async.wait_group %0;" :: "n"(n) : "memory")

// ================== split: fp32 -> (hi, lo) bf16 ==================
__global__ __launch_bounds__(256)
void split_f32(const float* __restrict__ src, __nv_bfloat16* __restrict__ hi,
               __nv_bfloat16* __restrict__ lo, int nsrc, int ntot) {
    int i = (blockIdx.x * 256 + threadIdx.x) * 4;
    if (i >= ntot) return;
    float4 v = (i < nsrc) ? *(const float4*)&src[i]
                          : make_float4(0.f, 0.f, 0.f, 0.f);
    float vs[4] = {v.x, v.y, v.z, v.w};
    union { __nv_bfloat16 b[4]; uint2 u; } ph, pl;
#pragma unroll
    for (int j = 0; j < 4; j++) {
        __nv_bfloat16 h = __float2bfloat16(vs[j]);
        ph.b[j] = h;
        pl.b[j] = __float2bfloat16(vs[j] - __bfloat162float(h));
    }
    *(uint2*)&hi[i] = ph.u;
    *(uint2*)&lo[i] = pl.u;
}

// ========== GEMM: C[M,N] = A[M,K]*B[N,K]^T, pre-split bf16, cp.async x3 ==========
// 512 threads, BM=BN=128, BK=32. SMEM row (128B): [hi 64B | lo 64B], SW128.
// MMA inner loop: 3 passes (hh, hl, lh) over 8 independent accumulators so
// dependent HMMAs to the same acc are 8 issues apart (latency hidden).
#define GBK2   32
#define ATILE  16384                  // 128 rows * 128B
#define STAGEB 32768                  // A tile + B tile
#define STAGES 3
#define GEMM_DSMEM (STAGES*STAGEB + 1024)

__global__ __launch_bounds__(512, 1)
void gemm_nt(const __nv_bfloat16* __restrict__ Ah, const __nv_bfloat16* __restrict__ Al,
             const __nv_bfloat16* __restrict__ Bh, const __nv_bfloat16* __restrict__ Bl,
             float* __restrict__ C, int M, int N, int K, int ldc) {
    extern __shared__ char dsm_raw[];
    const uint32_t dsm = (smem_u32(dsm_raw) + 1023u) & ~1023u;

    const int tid  = threadIdx.x;
    const int lane = tid & 31;
    const int warp = tid >> 5;           // 0..15
    const int wm   = warp >> 2;          // 0..3 -> 32-row band
    const int wn   = warp & 3;           // 0..3 -> 32-col band
    const int bm   = blockIdx.y * 128;
    const int bn   = blockIdx.x * 128;
    const int nk   = K / GBK2;

    // cp.async chunk mapping: 2 A-chunks + 2 B-chunks per thread (16B each)
    const int r_ld  = tid >> 2;          // 0..127
    const int c0_ld = (tid & 3) * 2;     // 0,2,4,6

    float acc[2][4][4];
#pragma unroll
    for (int a = 0; a < 2; a++)
#pragma unroll
        for (int b = 0; b < 4; b++)
#pragma unroll
            for (int c = 0; c < 4; c++) acc[a][b][c] = 0.f;

    auto issue = [&](int kt) {
        const uint32_t sA = dsm + (uint32_t)(kt % STAGES) * STAGEB;
        const uint32_t sB = sA + ATILE;
        const int kb = kt * GBK2;
#pragma unroll
        for (int q = 0; q < 2; q++) {
            const int c = c0_ld + q;                 // 0..7
            const __nv_bfloat16* s = (c < 4 ? Ah : Al)
                + (size_t)(bm + r_ld) * K + kb + (c & 3) * 8;
            cp16(sA + SMEM_SWZ((uint32_t)(r_ld * 128 + c * 16)), s);
        }
#pragma unroll
        for (int q = 0; q < 2; q++) {
            const int c = c0_ld + q;
            const __nv_bfloat16* s = (c < 4 ? Bh : Bl)
                + (size_t)(bn + r_ld) * K + kb + (c & 3) * 8;
            cp16(sB + SMEM_SWZ((uint32_t)(r_ld * 128 + c * 16)), s);
        }
    };

    issue(0); CP_COMMIT();
    issue(1); CP_COMMIT();

    for (int kt = 0; kt < nk; kt++) {
        CP_WAIT(1);
        __syncthreads();
        if (kt + 2 < nk) issue(kt + 2);
        CP_COMMIT();

        const uint32_t sA = dsm + (uint32_t)(kt % STAGES) * STAGEB;
        const uint32_t sB = sA + ATILE;
#pragma unroll
        for (int kk = 0; kk < 64; kk += 32) {        // byte offset of k16 slice
            uint32_t ah[2][4], alr[2][4], bh[2][4], bl[2][4];
#pragma unroll
            for (int mi = 0; mi < 2; mi++) {
                const uint32_t row = wm * 32 + mi * 16 + (lane & 15);
                const uint32_t o = row * 128 + kk + ((lane >> 4) << 4);
                ldsm4(sA + SMEM_SWZ(o),      ah[mi]);
                ldsm4(sA + SMEM_SWZ(o + 64), alr[mi]);
            }
#pragma unroll
            for (int ng = 0; ng < 2; ng++) {
                const uint32_t row = wn * 32 + ng * 16 + (lane & 7)
                                   + (((lane >> 4) & 1) << 3);
                const uint32_t o = row * 128 + kk + (((lane >> 3) & 1) << 4);
                ldsm4(sB + SMEM_SWZ(o),      bh[ng]);
                ldsm4(sB + SMEM_SWZ(o + 64), bl[ng]);
            }
            // pass 1: hi*hi over all 8 accumulators (independent issues)
#pragma unroll
            for (int mi = 0; mi < 2; mi++)
#pragma unroll
                for (int nj = 0; nj < 4; nj++) {
                    const int ng = nj >> 1, hf = nj & 1;
                    mma_bf16(acc[mi][nj], ah[mi],  bh[ng][hf*2], bh[ng][hf*2+1]);
                }
            // pass 2: hi*lo
#pragma unroll
            for (int mi = 0; mi < 2; mi++)
#pragma unroll
                for (int nj = 0; nj < 4; nj++) {
                    const int ng = nj >> 1, hf = nj & 1;
                    mma_bf16(acc[mi][nj], ah[mi],  bl[ng][hf*2], bl[ng][hf*2+1]);
                }
            // pass 3: lo*hi
#pragma unroll
            for (int mi = 0; mi < 2; mi++)
#pragma unroll
                for (int nj = 0; nj < 4; nj++) {
                    const int ng = nj >> 1, hf = nj & 1;
                    mma_bf16(acc[mi][nj], alr[mi], bh[ng][hf*2], bh[ng][hf*2+1]);
                }
        }
    }

    // epilogue
#pragma unroll
    for (int mi = 0; mi < 2; mi++)
#pragma unroll
        for (int nj = 0; nj < 4; nj++) {
            const int row = bm + wm * 32 + mi * 16 + (lane >> 2);
            const int col = bn + wn * 32 + nj * 8 + ((lane & 3) << 1);
            if (col < N) {
                *(float2*)&C[(size_t)row * ldc + col] =
                    make_float2(acc[mi][nj][0], acc[mi][nj][1]);
                *(float2*)&C[(size_t)(row + 8) * ldc + col] =
                    make_float2(acc[mi][nj][2], acc[mi][nj][3]);
            }
        }
}

// ---------------- scan ----------------
__device__ __forceinline__ float softplus_(float v) {
    return fmaxf(v, 0.f) + __logf(1.f + __expf(-fabsf(v)));
}

__global__ __launch_bounds__(256)
void scan_pass1(const float* __restrict__ x, const float* __restrict__ A_log) {
    const int h = blockIdx.x * 256 + threadIdx.x;
    const int b = blockIdx.y, c = blockIdx.z;
    const int m0 = b * SEQ + c * LC;

    __shared__ float bt_s[LC][NST];
    for (int i = threadIdx.x; i < LC * NST; i += 256) {
        int t = i >> 4, j = i & 15;
        bt_s[t][j] = g_xp[(size_t)(m0 + t) * XPC + j];
    }
    float A2[NST];
#pragma unroll
    for (int n = 0; n < NST; n++) A2[n] = -__expf(A_log[n]) * 1.44269504f;
    __syncthreads();

    float E[NST];
#pragma unroll
    for (int n = 0; n < NST; n++) E[n] = 0.f;
    float S = 0.f;

#pragma unroll 2
    for (int t = 0; t < LC; t++) {
        float dtr = g_xp[(size_t)(m0 + t) * XPC + 2*NST + h];
        float dt  = softplus_(dtr);
        float xv  = x[(size_t)(m0 + t) * HID + h];
        g_dt[(size_t)(m0 + t) * HID + h] = dt;
        S += dt;
        float dtx = dt * xv;
#pragma unroll
        for (int n = 0; n < NST; n++) {
            float dA = ex2_(A2[n] * dt);
            E[n] = fmaf(dA, E[n], bt_s[t][n] * dtx);
        }
    }
    const int cb = c * BATCHN + b;
#pragma unroll
    for (int n = 0; n < NST; n++)
        g_E[((size_t)cb * NST + n) * HID + h] = E[n];
    g_S[(size_t)cb * HID + h] = S;
}

__global__ __launch_bounds__(256)
void scan_combine(const float* __restrict__ A_log) {
    const int idx = blockIdx.x * 256 + threadIdx.x;
    const int h = idx & (HID - 1);
    const int n = (idx >> 10) & (NST - 1);
    const int b = idx >> 14;
    const float A2 = -__expf(A_log[n]) * 1.44269504f;

    float hr = 0.f;
    float Ecur = g_E[((size_t)(0 * BATCHN + b) * NST + n) * HID + h];
    float Scur = g_S[(size_t)(0 * BATCHN + b) * HID + h];

    for (int c = 0; c < NCHUNK; c++) {
        float Enext = 0.f, Snext = 0.f;
        if (c + 1 < NCHUNK) {
            const int cb1 = (c + 1) * BATCHN + b;
            Enext = g_E[((size_t)cb1 * NST + n) * HID + h];
            Snext = g_S[(size_t)cb1 * HID + h];
        }
        const int cb = c * BATCHN + b;
        g_h0[((size_t)cb * NST + n) * HID + h] = hr;
        hr = fmaf(ex2_(A2 * Scur), hr, Ecur);
        Ecur = Enext; Scur = Snext;
    }
}

// pass 2 -> writes split bf16 y directly (GEMM2's A operand)
__global__ __launch_bounds__(256)
void scan_pass2(const float* __restrict__ x, const float* __restrict__ A_log,
                const float* __restrict__ Dw) {
    const int h = blockIdx.x * 256 + threadIdx.x;
    const int b = blockIdx.y, c = blockIdx.z;
    const int m0 = b * SEQ + c * LC;

    __shared__ float bc_s[LC][2 * NST];
    for (int i = threadIdx.x; i < LC * 2 * NST; i += 256) {
        int t = i >> 5, j = i & 31;
        bc_s[t][j] = g_xp[(size_t)(m0 + t) * XPC + j];
    }
    float A2[NST];
#pragma unroll
    for (int n = 0; n < NST; n++) A2[n] = -__expf(A_log[n]) * 1.44269504f;
    __syncthreads();

    const int cb = c * BATCHN + b;
    float hreg[NST];
#pragma unroll
    for (int n = 0; n < NST; n++)
        hreg[n] = g_h0[((size_t)cb * NST + n) * HID + h];
    const float Dh = Dw[h];

#pragma unroll 2
    for (int t = 0; t < LC; t++) {
        float dt  = g_dt[(size_t)(m0 + t) * HID + h];
        float xv  = x[(size_t)(m0 + t) * HID + h];
        float dtx = dt * xv;
        float y   = Dh * xv;
#pragma unroll
        for (int n = 0; n < NST; n++) {
            float dA = ex2_(A2[n] * dt);
            hreg[n] = fmaf(dA, hreg[n], bc_s[t][n] * dtx);
            y = fmaf(bc_s[t][NST + n], hreg[n], y);
        }
        __nv_bfloat16 hb = __float2bfloat16(y);
        const size_t o = (size_t)(m0 + t) * HID + h;
        g_yh[o] = hb;
        g_yl[o] = __float2bfloat16(y - __bfloat162float(hb));
    }
}

// ---------------- launch ----------------
extern "C" void kernel_launch(void* const* d_in, const int* in_sizes, int n_in,
                              void* d_out, int out_size) {
    const float* x    = (const float*)d_in[0];
    const float* Wx   = (const float*)d_in[1];
    const float* Alog = (const float*)d_in[2];
    const float* Dw   = (const float*)d_in[3];
    const float* Wout = (const float*)d_in[4];
    for (int i = 0; i < n_in; i++) {
        const float* p = (const float*)d_in[i];
        switch (in_sizes[i]) {
            case M_ROWS * HID: x    = p; break;
            case XPC * HID:    Wx   = p; break;
            case NST:          Alog = p; break;
            case HID:          Dw   = p; break;
            case HID * HID:    Wout = p; break;
        }
    }

    float* xp_d = nullptr;
    cudaGetSymbolAddress((void**)&xp_d, g_xp);
    __nv_bfloat16 *xh, *xl, *wxh, *wxl, *wh, *wl, *yh, *yl;
    cudaGetSymbolAddress((void**)&xh,  g_xh);
    cudaGetSymbolAddress((void**)&xl,  g_xl);
    cudaGetSymbolAddress((void**)&wxh, g_wxh);
    cudaGetSymbolAddress((void**)&wxl, g_wxl);
    cudaGetSymbolAddress((void**)&wh,  g_wh);
    cudaGetSymbolAddress((void**)&wl,  g_wl);
    cudaGetSymbolAddress((void**)&yh,  g_yh);
    cudaGetSymbolAddress((void**)&yl,  g_yl);

    cudaFuncSetAttribute(gemm_nt, cudaFuncAttributeMaxDynamicSharedMemorySize,
                         GEMM_DSMEM);

    dim3 blk(256);
    dim3 gblk(512);
    // pre-split operands
    split_f32<<<M_ROWS*HID/1024, blk>>>(x,    xh,  xl,  M_ROWS*HID, M_ROWS*HID);
    split_f32<<<NPAD1*HID/1024,  blk>>>(Wx,   wxh, wxl, XPC*HID,    NPAD1*HID);
    split_f32<<<HID*HID/1024,    blk>>>(Wout, wh,  wl,  HID*HID,    HID*HID);

    // GEMM1: g_xp = x @ Wx^T   (M=8192, N=1056 padded 1152, K=1024)
    gemm_nt<<<dim3(NPAD1/128, M_ROWS/128), gblk, GEMM_DSMEM>>>(
        xh, xl, wxh, wxl, xp_d, M_ROWS, XPC, HID, XPC);

    // chunked selective scan
    scan_pass1 <<<dim3(HID / 256, BATCHN, NCHUNK), blk>>>(x, Alog);
    scan_combine<<<BATCHN * NST * HID / 256, blk>>>(Alog);
    scan_pass2 <<<dim3(HID / 256, BATCHN, NCHUNK), blk>>>(x, Alog, Dw);

    // GEMM2: out = y @ Wout^T  (M=8192, N=1024, K=1024)
    gemm_nt<<<dim3(HID/128, M_ROWS/128), gblk, GEMM_DSMEM>>>(
        yh, yl, wh, wl, (float*)d_out, M_ROWS, HID, HID, HID);
}